// round 11
// baseline (speedup 1.0000x reference)
#include <cuda_runtime.h>
#include <cuda_fp16.h>
#include <cstdint>

#define Bdim  4
#define Sdim  1024
#define Hdim  1024
#define ENTn  16
#define INNER 64
#define NOUT  2048
#define NEGC  1.0e12f

// Scratch (allocation-free rule: __device__ globals)
__device__ __half g_Q[Bdim*ENTn*Sdim*INNER];   // [b][h][s][d] f16
__device__ __half g_K[Bdim*ENTn*Sdim*INNER];
__device__ __half g_Xh[Bdim*Sdim*Hdim];        // X in f16 [m][k]
__device__ __half g_Wt[NOUT*Hdim];             // W^T in f16 [n][k]
__device__ float g_sin[Sdim*(INNER/2)];        // [s][j]
__device__ float g_cos[Sdim*(INNER/2)];

__device__ __forceinline__ void cp16(void* s, const void* g){
    uint32_t sa = (uint32_t)__cvta_generic_to_shared(s);
    asm volatile("cp.async.cg.shared.global [%0], [%1], 16;" :: "r"(sa), "l"(g));
}
__device__ __forceinline__ void cp_commit(){ asm volatile("cp.async.commit_group;" ::: "memory"); }
template<int N> __device__ __forceinline__ void cp_wait(){
    asm volatile("cp.async.wait_group %0;" :: "n"(N) : "memory");
}
__device__ __forceinline__ void ldsm_x4(uint32_t* r, uint32_t addr){
    asm volatile("ldmatrix.sync.aligned.m8n8.x4.shared.b16 {%0,%1,%2,%3}, [%4];"
        : "=r"(r[0]), "=r"(r[1]), "=r"(r[2]), "=r"(r[3]) : "r"(addr));
}
// f16 inputs, f16 accumulators (2 C regs)
__device__ __forceinline__ void mma_f16acc(uint32_t* c, const uint32_t* a, const uint32_t* b){
    asm volatile("mma.sync.aligned.m16n8k16.row.col.f16.f16.f16.f16 "
        "{%0,%1}, {%2,%3,%4,%5}, {%6,%7}, {%0,%1};"
        : "+r"(c[0]), "+r"(c[1])
        : "r"(a[0]), "r"(a[1]), "r"(a[2]), "r"(a[3]), "r"(b[0]), "r"(b[1]));
}
// f16 inputs, f32 accumulators (attn)
__device__ __forceinline__ void mma_f32acc(float* c, const uint32_t* a, const uint32_t* b){
    asm volatile("mma.sync.aligned.m16n8k16.row.col.f32.f16.f16.f32 "
        "{%0,%1,%2,%3}, {%4,%5,%6,%7}, {%8,%9}, {%0,%1,%2,%3};"
        : "+f"(c[0]), "+f"(c[1]), "+f"(c[2]), "+f"(c[3])
        : "r"(a[0]), "r"(a[1]), "r"(a[2]), "r"(a[3]), "r"(b[0]), "r"(b[1]));
}
__device__ __forceinline__ void stg_cs_f2(float* p, float x, float y){
    asm volatile("st.global.cs.v2.f32 [%0], {%1,%2};" :: "l"(p), "f"(x), "f"(y) : "memory");
}
__device__ __forceinline__ void stg_cs_f4(float* p, float4 v){
    asm volatile("st.global.cs.v4.f32 [%0], {%1,%2,%3,%4};"
        :: "l"(p), "f"(v.x), "f"(v.y), "f"(v.z), "f"(v.w) : "memory");
}

// ---------------------------------------------------------------------------
// Kernel T: RoPE sin/cos table (exact fp32 math matching jax reference)
// ---------------------------------------------------------------------------
__global__ void sincos_kernel(){
    int idx = blockIdx.x*blockDim.x + threadIdx.x;
    if (idx >= Sdim*32) return;
    int s = idx >> 5, j = idx & 31;
    float freq = powf(10000.0f, -(float)j * 0.03125f);
    float ang  = (float)s * freq;
    g_sin[idx] = sinf(ang);
    g_cos[idx] = cosf(ang);
}

// ---------------------------------------------------------------------------
// Prep: X (f32) -> g_Xh (f16)
// ---------------------------------------------------------------------------
__global__ void prep_x_kernel(const float* __restrict__ X){
    int n2 = Bdim*Sdim*Hdim/2;
    for (int i = blockIdx.x*blockDim.x + threadIdx.x; i < n2; i += gridDim.x*blockDim.x){
        float2 v = reinterpret_cast<const float2*>(X)[i];
        __half2 o;
        o.x = __float2half_rn(v.x);
        o.y = __float2half_rn(v.y);
        reinterpret_cast<__half2*>(g_Xh)[i] = o;
    }
}

// ---------------------------------------------------------------------------
// Prep: W [k][n] f32 -> g_Wt [n][k] f16 (tiled transpose)
// ---------------------------------------------------------------------------
__global__ void prep_w_kernel(const float* __restrict__ W){
    __shared__ float t[32][33];
    const int k0 = blockIdx.y*32, n0 = blockIdx.x*32;
    #pragma unroll
    for (int i = threadIdx.y; i < 32; i += 8)
        t[i][threadIdx.x] = W[(size_t)(k0+i)*NOUT + n0 + threadIdx.x];
    __syncthreads();
    #pragma unroll
    for (int i = threadIdx.y; i < 32; i += 8)
        g_Wt[(size_t)(n0+i)*Hdim + k0 + threadIdx.x] = __float2half_rn(t[threadIdx.x][i]);
}

// ---------------------------------------------------------------------------
// Kernel A: C = X@W + b, fused interleaved RoPE, scatter to g_Q/g_K (f16).
// M=4096, N=2048, K=1024. CTA tile 128x256, 256 threads (2x4 warps of 64x64),
// f16 accumulators. BK=32, 3-stage cp.async ring, ONE __syncthreads per
// k-block (load for ks+2 targets the buffer freed at ks-1, protected by the
// sync at iteration ks). Stride 40 halves: conflict-free LDSM, 16B aligned.
// 92KB smem -> 2 CTAs/SM (16 warps/SM); grid 256 = one wave.
// ---------------------------------------------------------------------------
#define G1STR 40
#define ST_HALVES ((128+256)*G1STR)              // 15360 halves = 30720 B
#define SMEM_A_BYTES (3*ST_HALVES*2)             // 92160 B

__global__ void __launch_bounds__(256, 2) gemm1_rope_kernel(
    const float* __restrict__ bias)
{
    extern __shared__ __half smb[];
    const uint32_t sbase = (uint32_t)__cvta_generic_to_shared(smb);
    const int tid  = threadIdx.x;
    const int lane = tid & 31, warp = tid >> 5;
    const int g = lane >> 2, tg = lane & 3;
    const int wm = warp >> 2, wn = warp & 3;          // 2x4 warps, 64x64 tiles
    const int mtile = blockIdx.y, ntile = blockIdx.x; // grid (8, 32)
    const __half* Xb = g_Xh + (size_t)mtile*128*Hdim;
    const __half* Wb = g_Wt + (size_t)ntile*256*Hdim;

    const int l7   = lane & 7;
    const int selA_r = ((lane >> 3) & 1) * 8;
    const int selA_c = (lane >> 4) * 8;
    const int selB_r = (lane >> 4) * 8;
    const int selB_c = ((lane >> 3) & 1) * 8;

    uint32_t acc[4][8][2];                            // f16x2 accumulators
    #pragma unroll
    for (int a=0;a<4;a++)
        #pragma unroll
        for (int bq=0;bq<8;bq++){ acc[a][bq][0]=0u; acc[a][bq][1]=0u; }

    auto load_stage = [&](int ks){
        __half* Sd = smb + (ks%3)*ST_HALVES;
        const __half* xs = Xb + ks*32;
        const __half* ws = Wb + ks*32;
        #pragma unroll
        for (int i=0;i<2;i++){                    // A: 512 chunks
            int c = tid + i*256;
            int row = c >> 2, ch = (c & 3) << 3;  // 128 rows x 4 chunks of 8 halves
            cp16(Sd + row*G1STR + ch, xs + (size_t)row*Hdim + ch);
        }
        __half* Bd = Sd + 128*G1STR;
        #pragma unroll
        for (int i=0;i<4;i++){                    // B: 1024 chunks
            int c = tid + i*256;
            int row = c >> 2, ch = (c & 3) << 3;  // 256 rows x 4 chunks
            cp16(Bd + row*G1STR + ch, ws + (size_t)row*Hdim + ch);
        }
        cp_commit();
    };

    load_stage(0); load_stage(1);
    for (int ks = 0; ks < 32; ks++){
        if (ks < 31) cp_wait<1>(); else cp_wait<0>();
        __syncthreads();
        if (ks + 2 < 32) load_stage(ks + 2);      // into buffer freed at ks-1

        const uint32_t stb = sbase + (ks%3)*ST_HALVES*2;
        const uint32_t abase = stb;
        const uint32_t bbase = stb + 128*G1STR*2;
        #pragma unroll
        for (int kk=0; kk<2; kk++){
            const int k0 = kk*16;
            uint32_t af[4][4], bf[8][2];
            #pragma unroll
            for (int mt=0; mt<4; mt++){
                int row = wm*64 + mt*16 + selA_r + l7;
                ldsm_x4(af[mt], abase + (row*G1STR + k0 + selA_c)*2);
            }
            #pragma unroll
            for (int ntp=0; ntp<4; ntp++){
                int row = wn*64 + ntp*16 + selB_r + l7;
                uint32_t q[4];
                ldsm_x4(q, bbase + (row*G1STR + k0 + selB_c)*2);
                bf[2*ntp  ][0] = q[0]; bf[2*ntp  ][1] = q[1];
                bf[2*ntp+1][0] = q[2]; bf[2*ntp+1][1] = q[3];
            }
            #pragma unroll
            for (int mt=0; mt<4; mt++)
                #pragma unroll
                for (int nt=0; nt<8; nt++)
                    mma_f16acc(acc[mt][nt], af[mt], bf[nt]);
        }
    }

    // Epilogue: bias + RoPE (interleaved pair == packed half2 lanes), f16 out
    #pragma unroll
    for (int nt=0; nt<8; nt++){
        const int n_loc = wn*64 + nt*8 + 2*tg;
        const int c = ntile*256 + n_loc;         // even
        const int h = c >> 7, r = c & 127;
        const int d = r & 63, jj = d >> 1;
        __half* dst = (r < 64) ? g_Q : g_K;
        const float b0 = bias[c], b1 = bias[c+1];
        #pragma unroll
        for (int mt=0; mt<4; mt++){
            #pragma unroll
            for (int p=0; p<2; p++){
                int m = mtile*128 + wm*64 + mt*16 + g + p*8;
                int bb = m >> 10, s = m & 1023;
                float sv = g_sin[s*32 + jj], cv = g_cos[s*32 + jj];
                __half2 hv = *reinterpret_cast<__half2*>(&acc[mt][nt][p]);
                float v0 = __half2float(hv.x) + b0;
                float v1 = __half2float(hv.y) + b1;
                __half2 o;
                o.x = __float2half_rn(v0*cv - v1*sv);
                o.y = __float2half_rn(v1*cv + v0*sv);
                int idx = ((bb*ENTn + h)*Sdim + s)*INNER + d;
                *reinterpret_cast<__half2*>(dst + idx) = o;
            }
        }
    }
}

// ---------------------------------------------------------------------------
// Kernel B: logits[z=(b,h)][m][n] = (Q[m]·K[n]) masked/scaled. 128x128 tiles.
// Strictly-lower tiles: exact constant, streaming float4 stores.
// Upper/diagonal: f16 m16n8k16 (f32 acc) over d=64, ldmatrix fragment loads,
// streaming (st.global.cs) output stores.
// ---------------------------------------------------------------------------
#define QK2STR 72
#define SMEM_B_BYTES (2*128*QK2STR*2)

__global__ void __launch_bounds__(256) attn_logits_kernel(
    const float* __restrict__ tok, float* __restrict__ out)
{
    const int ntile = blockIdx.x, mtile = blockIdx.y, z = blockIdx.z;
    const int bidx = z >> 4;
    const int tid = threadIdx.x;
    float* outb = out + ((size_t)z << 20);
    const float* padp = tok + bidx*Sdim + ntile*128;

    if (ntile < mtile){
        const int n4 = (tid & 31) << 2;
        const int m0 = mtile*128 + (tid >> 5);
        float4 pv = *reinterpret_cast<const float4*>(padp + n4);
        float4 val;
        val.x = (-(1.0f - pv.x)*NEGC - NEGC)*0.125f;
        val.y = (-(1.0f - pv.y)*NEGC - NEGC)*0.125f;
        val.z = (-(1.0f - pv.z)*NEGC - NEGC)*0.125f;
        val.w = (-(1.0f - pv.w)*NEGC - NEGC)*0.125f;
        const int ncol = ntile*128 + n4;
        #pragma unroll
        for (int i=0;i<16;i++)
            stg_cs_f4(outb + ((size_t)(m0 + i*8) << 10) + ncol, val);
        return;
    }

    extern __shared__ __half smh[];
    const uint32_t sbase = (uint32_t)__cvta_generic_to_shared(smh);
    __half* Qs = smh;                 // [128][QK2STR]
    __half* Ks = smh + 128*QK2STR;
    __shared__ float pad_s[128];
    if (tid < 128) pad_s[tid] = padp[tid];

    const __half* Qg = g_Q + ((size_t)z*Sdim + (size_t)mtile*128)*INNER;
    const __half* Kg = g_K + ((size_t)z*Sdim + (size_t)ntile*128)*INNER;
    #pragma unroll
    for (int i=0;i<4;i++){
        int t = tid + i*256;
        int row = t >> 3, ch = (t & 7) << 3;
        cp16(Qs + row*QK2STR + ch, Qg + row*INNER + ch);
        cp16(Ks + row*QK2STR + ch, Kg + row*INNER + ch);
    }
    cp_commit();
    cp_wait<0>();
    __syncthreads();

    const int lane = tid & 31, warp = tid >> 5;
    const int g = lane >> 2, tg = lane & 3;
    const int wm = warp >> 1, wn = warp & 1;
    const int l7   = lane & 7;
    const int selA_r = ((lane >> 3) & 1) * 8;
    const int selA_c = (lane >> 4) * 8;
    const int selB_r = (lane >> 4) * 8;
    const int selB_c = ((lane >> 3) & 1) * 8;
    const uint32_t qbase = sbase;
    const uint32_t kbase = sbase + (128*QK2STR)*2;

    float acc[2][8][4];
    #pragma unroll
    for (int a=0;a<2;a++)
        #pragma unroll
        for (int bq=0;bq<8;bq++)
            #pragma unroll
            for (int k=0;k<4;k++) acc[a][bq][k]=0.f;

    #pragma unroll
    for (int kk=0; kk<4; kk++){
        const int k0 = kk*16;
        uint32_t af[2][4], bf[8][2];
        #pragma unroll
        for (int mt=0; mt<2; mt++){
            int row = wm*32 + mt*16 + selA_r + l7;
            ldsm_x4(af[mt], qbase + (row*QK2STR + k0 + selA_c)*2);
        }
        #pragma unroll
        for (int ntp=0; ntp<4; ntp++){
            int row = wn*64 + ntp*16 + selB_r + l7;
            uint32_t q[4];
            ldsm_x4(q, kbase + (row*QK2STR + k0 + selB_c)*2);
            bf[2*ntp  ][0] = q[0]; bf[2*ntp  ][1] = q[1];
            bf[2*ntp+1][0] = q[2]; bf[2*ntp+1][1] = q[3];
        }
        #pragma unroll
        for (int mt=0; mt<2; mt++)
            #pragma unroll
            for (int nt=0; nt<8; nt++)
                mma_f32acc(acc[mt][nt], af[mt], bf[nt]);
    }

    #pragma unroll
    for (int mt=0; mt<2; mt++){
        #pragma unroll
        for (int nt=0; nt<8; nt++){
            const int n_loc = wn*64 + nt*8 + 2*tg;
            const int n = ntile*128 + n_loc;
            const float p0 = pad_s[n_loc], p1 = pad_s[n_loc+1];
            #pragma unroll
            for (int p=0; p<2; p++){
                const int m = mtile*128 + wm*32 + mt*16 + g + p*8;
                float v0 = acc[mt][nt][2*p]   * p0 - (1.0f - p0)*NEGC - ((n   < m) ? NEGC : 0.0f);
                float v1 = acc[mt][nt][2*p+1] * p1 - (1.0f - p1)*NEGC - ((n+1 < m) ? NEGC : 0.0f);
                stg_cs_f2(outb + ((size_t)m << 10) + n, v0*0.125f, v1*0.125f);
            }
        }
    }
}

// ---------------------------------------------------------------------------
extern "C" void kernel_launch(void* const* d_in, const int* in_sizes, int n_in,
                              void* d_out, int out_size)
{
    const float* X    = (const float*)d_in[0];
    const float* W    = (const float*)d_in[1];
    const float* bias = (const float*)d_in[2];
    const float* tok  = (const float*)d_in[3];
    float* out = (float*)d_out;

    cudaFuncSetAttribute(gemm1_rope_kernel,
        cudaFuncAttributeMaxDynamicSharedMemorySize, SMEM_A_BYTES);
    cudaFuncSetAttribute(attn_logits_kernel,
        cudaFuncAttributeMaxDynamicSharedMemorySize, SMEM_B_BYTES);

    sincos_kernel<<<64, 512>>>();
    prep_x_kernel<<<512, 256>>>(X);
    prep_w_kernel<<<dim3(64, 32), dim3(32, 8)>>>(W);
    gemm1_rope_kernel<<<dim3(8, 32), 256, SMEM_A_BYTES>>>(bias);
    attn_logits_kernel<<<dim3(8, 8, 64), 256, SMEM_B_BYTES>>>(tok, out);
}

// round 12
// speedup vs baseline: 1.0680x; 1.0680x over previous
#include <cuda_runtime.h>
#include <cuda_fp16.h>
#include <cstdint>

#define Bdim  4
#define Sdim  1024
#define Hdim  1024
#define ENTn  16
#define INNER 64
#define NOUT  2048
#define NEGC  1.0e12f

// Scratch (allocation-free rule: __device__ globals)
__device__ __half g_Q[Bdim*ENTn*Sdim*INNER];   // [b][h][s][d] f16
__device__ __half g_K[Bdim*ENTn*Sdim*INNER];
__device__ __half g_Xh[Bdim*Sdim*Hdim];        // X in f16 [m][k]
__device__ __half g_Wt[NOUT*Hdim];             // W^T in f16 [n][k]
__device__ float g_sin[Sdim*(INNER/2)];        // [s][j]
__device__ float g_cos[Sdim*(INNER/2)];

__device__ __forceinline__ void cp16(void* s, const void* g){
    uint32_t sa = (uint32_t)__cvta_generic_to_shared(s);
    asm volatile("cp.async.cg.shared.global [%0], [%1], 16;" :: "r"(sa), "l"(g));
}
__device__ __forceinline__ void cp_commit(){ asm volatile("cp.async.commit_group;" ::: "memory"); }
template<int N> __device__ __forceinline__ void cp_wait(){
    asm volatile("cp.async.wait_group %0;" :: "n"(N) : "memory");
}
__device__ __forceinline__ void ldsm_x4(uint32_t* r, uint32_t addr){
    asm volatile("ldmatrix.sync.aligned.m8n8.x4.shared.b16 {%0,%1,%2,%3}, [%4];"
        : "=r"(r[0]), "=r"(r[1]), "=r"(r[2]), "=r"(r[3]) : "r"(addr));
}
// f16 inputs, f16 accumulators (2 C regs)
__device__ __forceinline__ void mma_f16acc(uint32_t* c, const uint32_t* a, const uint32_t* b){
    asm volatile("mma.sync.aligned.m16n8k16.row.col.f16.f16.f16.f16 "
        "{%0,%1}, {%2,%3,%4,%5}, {%6,%7}, {%0,%1};"
        : "+r"(c[0]), "+r"(c[1])
        : "r"(a[0]), "r"(a[1]), "r"(a[2]), "r"(a[3]), "r"(b[0]), "r"(b[1]));
}
// f16 inputs, f32 accumulators (attn)
__device__ __forceinline__ void mma_f32acc(float* c, const uint32_t* a, const uint32_t* b){
    asm volatile("mma.sync.aligned.m16n8k16.row.col.f32.f16.f16.f32 "
        "{%0,%1,%2,%3}, {%4,%5,%6,%7}, {%8,%9}, {%0,%1,%2,%3};"
        : "+f"(c[0]), "+f"(c[1]), "+f"(c[2]), "+f"(c[3])
        : "r"(a[0]), "r"(a[1]), "r"(a[2]), "r"(a[3]), "r"(b[0]), "r"(b[1]));
}
__device__ __forceinline__ void stg_cs_f2(float* p, float x, float y){
    asm volatile("st.global.cs.v2.f32 [%0], {%1,%2};" :: "l"(p), "f"(x), "f"(y) : "memory");
}
__device__ __forceinline__ void stg_cs_f4(float* p, float4 v){
    asm volatile("st.global.cs.v4.f32 [%0], {%1,%2,%3,%4};"
        :: "l"(p), "f"(v.x), "f"(v.y), "f"(v.z), "f"(v.w) : "memory");
}

// ---------------------------------------------------------------------------
// Kernel T: RoPE sin/cos table (exact fp32 math matching jax reference)
// ---------------------------------------------------------------------------
__global__ void sincos_kernel(){
    int idx = blockIdx.x*blockDim.x + threadIdx.x;
    if (idx >= Sdim*32) return;
    int s = idx >> 5, j = idx & 31;
    float freq = powf(10000.0f, -(float)j * 0.03125f);
    float ang  = (float)s * freq;
    g_sin[idx] = sinf(ang);
    g_cos[idx] = cosf(ang);
}

// ---------------------------------------------------------------------------
// Prep: X (f32) -> g_Xh (f16)
// ---------------------------------------------------------------------------
__global__ void prep_x_kernel(const float* __restrict__ X){
    int n2 = Bdim*Sdim*Hdim/2;
    for (int i = blockIdx.x*blockDim.x + threadIdx.x; i < n2; i += gridDim.x*blockDim.x){
        float2 v = reinterpret_cast<const float2*>(X)[i];
        __half2 o;
        o.x = __float2half_rn(v.x);
        o.y = __float2half_rn(v.y);
        reinterpret_cast<__half2*>(g_Xh)[i] = o;
    }
}

// ---------------------------------------------------------------------------
// Prep: W [k][n] f32 -> g_Wt [n][k] f16 (tiled transpose)
// ---------------------------------------------------------------------------
__global__ void prep_w_kernel(const float* __restrict__ W){
    __shared__ float t[32][33];
    const int k0 = blockIdx.y*32, n0 = blockIdx.x*32;
    #pragma unroll
    for (int i = threadIdx.y; i < 32; i += 8)
        t[i][threadIdx.x] = W[(size_t)(k0+i)*NOUT + n0 + threadIdx.x];
    __syncthreads();
    #pragma unroll
    for (int i = threadIdx.y; i < 32; i += 8)
        g_Wt[(size_t)(n0+i)*Hdim + k0 + threadIdx.x] = __float2half_rn(t[threadIdx.x][i]);
}

// ---------------------------------------------------------------------------
// Kernel A (fused): bid < 512  -> GEMM1 + RoPE (R10 config: 128 thr, 2x2
//   warps of 64x64, BK=32, 2-stage, stride 40 — measured 68.7us).
// bid >= 512 -> constant-fill CTA for one strictly-lower logits tile
//   (1792 = 64 z x 28 tiles). These stream 128 MB of exact-constant output
//   into the DRAM bandwidth the GEMM leaves idle (2.5% busy).
// ---------------------------------------------------------------------------
#define G1STR 40
#define SMEM_A_BYTES (4*128*G1STR*2)   // A[2] + B[2] buffers, 40960 B
#define GEMM_CTAS 512
#define FILL_CTAS (64*28)

__global__ void __launch_bounds__(128, 4) gemm1_rope_fill_kernel(
    const float* __restrict__ bias, const float* __restrict__ tok,
    float* __restrict__ out)
{
    const int bid = blockIdx.x;
    const int tid = threadIdx.x;

    if (bid >= GEMM_CTAS){
        // ---- constant fill of one strictly-lower 128x128 tile ----
        int f = bid - GEMM_CTAS;
        int z = f / 28, t = f % 28;
        int mt = 1; while (t >= mt){ t -= mt; mt++; }   // mtile=mt (1..7), ntile=t
        const int ntile = t;
        float* outb = out + ((size_t)z << 20);
        const float* padp = tok + (z >> 4)*Sdim + ntile*128;

        const int n4 = (tid & 31) << 2;
        const int m0 = mt*128 + (tid >> 5);             // 4 warps -> rows tid>>5 + i*4
        float4 pv = *reinterpret_cast<const float4*>(padp + n4);
        float4 val;
        val.x = (-(1.0f - pv.x)*NEGC - NEGC)*0.125f;
        val.y = (-(1.0f - pv.y)*NEGC - NEGC)*0.125f;
        val.z = (-(1.0f - pv.z)*NEGC - NEGC)*0.125f;
        val.w = (-(1.0f - pv.w)*NEGC - NEGC)*0.125f;
        const int ncol = ntile*128 + n4;
        #pragma unroll
        for (int i = 0; i < 32; i++)
            stg_cs_f4(outb + ((size_t)(m0 + i*4) << 10) + ncol, val);
        return;
    }

    // ---- GEMM1 + RoPE (identical to R10 best) ----
    extern __shared__ __half smb[];
    const uint32_t sbase = (uint32_t)__cvta_generic_to_shared(smb);
    const int lane = tid & 31, warp = tid >> 5;
    const int g = lane >> 2, tg = lane & 3;
    const int wm = warp >> 1, wn = warp & 1;          // 2x2 warps, 64x64 tiles
    const int ntile = bid & 15, mtile = bid >> 4;     // 16 x 32
    const __half* Xb = g_Xh + (size_t)mtile*128*Hdim;
    const __half* Wb = g_Wt + (size_t)ntile*128*Hdim;

    const int l7   = lane & 7;
    const int selA_r = ((lane >> 3) & 1) * 8;
    const int selA_c = (lane >> 4) * 8;
    const int selB_r = (lane >> 4) * 8;
    const int selB_c = ((lane >> 3) & 1) * 8;

    uint32_t acc[4][8][2];                            // f16x2 accumulators
    #pragma unroll
    for (int a=0;a<4;a++)
        #pragma unroll
        for (int bq=0;bq<8;bq++){ acc[a][bq][0]=0u; acc[a][bq][1]=0u; }

    auto load_stage = [&](int ks, int b){
        __half* Ad = smb + b*128*G1STR;
        __half* Bd = smb + (2+b)*128*G1STR;
        const __half* xs = Xb + ks*32;
        const __half* ws = Wb + ks*32;
        #pragma unroll
        for (int i=0;i<4;i++){
            int c = tid + i*128;                 // 0..511
            int row = c >> 2, ch = (c & 3) << 3; // 128 rows x 4 chunks of 8 halves
            cp16(Ad + row*G1STR + ch, xs + (size_t)row*Hdim + ch);
            cp16(Bd + row*G1STR + ch, ws + (size_t)row*Hdim + ch);
        }
        cp_commit();
    };

    load_stage(0, 0);
    int buf = 0;
    for (int ks = 0; ks < 32; ks++){
        if (ks < 31){ load_stage(ks+1, buf^1); cp_wait<1>(); }
        else        { cp_wait<0>(); }
        __syncthreads();
        const uint32_t abase = sbase + (buf*128*G1STR)*2;
        const uint32_t bbase = sbase + ((2+buf)*128*G1STR)*2;
        #pragma unroll
        for (int kk=0; kk<2; kk++){
            const int k0 = kk*16;
            uint32_t af[4][4], bf[8][2];
            #pragma unroll
            for (int mt=0; mt<4; mt++){
                int row = wm*64 + mt*16 + selA_r + l7;
                ldsm_x4(af[mt], abase + (row*G1STR + k0 + selA_c)*2);
            }
            #pragma unroll
            for (int ntp=0; ntp<4; ntp++){
                int row = wn*64 + ntp*16 + selB_r + l7;
                uint32_t q[4];
                ldsm_x4(q, bbase + (row*G1STR + k0 + selB_c)*2);
                bf[2*ntp  ][0] = q[0]; bf[2*ntp  ][1] = q[1];
                bf[2*ntp+1][0] = q[2]; bf[2*ntp+1][1] = q[3];
            }
            #pragma unroll
            for (int mt=0; mt<4; mt++)
                #pragma unroll
                for (int nt=0; nt<8; nt++)
                    mma_f16acc(acc[mt][nt], af[mt], bf[nt]);
        }
        __syncthreads();
        buf ^= 1;
    }

    // Epilogue: bias + RoPE (interleaved pair == packed half2 lanes), f16 out
    #pragma unroll
    for (int nt=0; nt<8; nt++){
        const int n_loc = wn*64 + nt*8 + 2*tg;
        const int c = ntile*128 + n_loc;         // even
        const int h = c >> 7, r = c & 127;
        const int d = r & 63, jj = d >> 1;
        __half* dst = (r < 64) ? g_Q : g_K;
        const float b0 = bias[c], b1 = bias[c+1];
        #pragma unroll
        for (int mt=0; mt<4; mt++){
            #pragma unroll
            for (int p=0; p<2; p++){
                int m = mtile*128 + wm*64 + mt*16 + g + p*8;
                int bb = m >> 10, s = m & 1023;
                float sv = g_sin[s*32 + jj], cv = g_cos[s*32 + jj];
                __half2 hv = *reinterpret_cast<__half2*>(&acc[mt][nt][p]);
                float v0 = __half2float(hv.x) + b0;
                float v1 = __half2float(hv.y) + b1;
                __half2 o;
                o.x = __float2half_rn(v0*cv - v1*sv);
                o.y = __float2half_rn(v1*cv + v0*sv);
                int idx = ((bb*ENTn + h)*Sdim + s)*INNER + d;
                *reinterpret_cast<__half2*>(dst + idx) = o;
            }
        }
    }
}

// ---------------------------------------------------------------------------
// Kernel B: upper/diagonal logits tiles only (lower tiles pre-filled by
// kernel A's filler CTAs). f16 m16n8k16 (f32 acc), ldmatrix, streaming stores.
// ---------------------------------------------------------------------------
#define QK2STR 72
#define SMEM_B_BYTES (2*128*QK2STR*2)

__global__ void __launch_bounds__(256) attn_logits_kernel(
    const float* __restrict__ tok, float* __restrict__ out)
{
    const int ntile = blockIdx.x, mtile = blockIdx.y, z = blockIdx.z;
    if (ntile < mtile) return;                 // pre-filled by kernel A
    const int bidx = z >> 4;
    const int tid = threadIdx.x;
    float* outb = out + ((size_t)z << 20);
    const float* padp = tok + bidx*Sdim + ntile*128;

    extern __shared__ __half smh[];
    const uint32_t sbase = (uint32_t)__cvta_generic_to_shared(smh);
    __half* Qs = smh;                 // [128][QK2STR]
    __half* Ks = smh + 128*QK2STR;
    __shared__ float pad_s[128];
    if (tid < 128) pad_s[tid] = padp[tid];

    const __half* Qg = g_Q + ((size_t)z*Sdim + (size_t)mtile*128)*INNER;
    const __half* Kg = g_K + ((size_t)z*Sdim + (size_t)ntile*128)*INNER;
    #pragma unroll
    for (int i=0;i<4;i++){
        int t = tid + i*256;
        int row = t >> 3, ch = (t & 7) << 3;
        cp16(Qs + row*QK2STR + ch, Qg + row*INNER + ch);
        cp16(Ks + row*QK2STR + ch, Kg + row*INNER + ch);
    }
    cp_commit();
    cp_wait<0>();
    __syncthreads();

    const int lane = tid & 31, warp = tid >> 5;
    const int g = lane >> 2, tg = lane & 3;
    const int wm = warp >> 1, wn = warp & 1;
    const int l7   = lane & 7;
    const int selA_r = ((lane >> 3) & 1) * 8;
    const int selA_c = (lane >> 4) * 8;
    const int selB_r = (lane >> 4) * 8;
    const int selB_c = ((lane >> 3) & 1) * 8;
    const uint32_t qbase = sbase;
    const uint32_t kbase = sbase + (128*QK2STR)*2;

    float acc[2][8][4];
    #pragma unroll
    for (int a=0;a<2;a++)
        #pragma unroll
        for (int bq=0;bq<8;bq++)
            #pragma unroll
            for (int k=0;k<4;k++) acc[a][bq][k]=0.f;

    #pragma unroll
    for (int kk=0; kk<4; kk++){
        const int k0 = kk*16;
        uint32_t af[2][4], bf[8][2];
        #pragma unroll
        for (int mt=0; mt<2; mt++){
            int row = wm*32 + mt*16 + selA_r + l7;
            ldsm_x4(af[mt], qbase + (row*QK2STR + k0 + selA_c)*2);
        }
        #pragma unroll
        for (int ntp=0; ntp<4; ntp++){
            int row = wn*64 + ntp*16 + selB_r + l7;
            uint32_t q[4];
            ldsm_x4(q, kbase + (row*QK2STR + k0 + selB_c)*2);
            bf[2*ntp  ][0] = q[0]; bf[2*ntp  ][1] = q[1];
            bf[2*ntp+1][0] = q[2]; bf[2*ntp+1][1] = q[3];
        }
        #pragma unroll
        for (int mt=0; mt<2; mt++)
            #pragma unroll
            for (int nt=0; nt<8; nt++)
                mma_f32acc(acc[mt][nt], af[mt], bf[nt]);
    }

    #pragma unroll
    for (int mt=0; mt<2; mt++){
        #pragma unroll
        for (int nt=0; nt<8; nt++){
            const int n_loc = wn*64 + nt*8 + 2*tg;
            const int n = ntile*128 + n_loc;
            const float p0 = pad_s[n_loc], p1 = pad_s[n_loc+1];
            #pragma unroll
            for (int p=0; p<2; p++){
                const int m = mtile*128 + wm*32 + mt*16 + g + p*8;
                float v0 = acc[mt][nt][2*p]   * p0 - (1.0f - p0)*NEGC - ((n   < m) ? NEGC : 0.0f);
                float v1 = acc[mt][nt][2*p+1] * p1 - (1.0f - p1)*NEGC - ((n+1 < m) ? NEGC : 0.0f);
                stg_cs_f2(outb + ((size_t)m << 10) + n, v0*0.125f, v1*0.125f);
            }
        }
    }
}

// ---------------------------------------------------------------------------
extern "C" void kernel_launch(void* const* d_in, const int* in_sizes, int n_in,
                              void* d_out, int out_size)
{
    const float* X    = (const float*)d_in[0];
    const float* W    = (const float*)d_in[1];
    const float* bias = (const float*)d_in[2];
    const float* tok  = (const float*)d_in[3];
    float* out = (float*)d_out;

    cudaFuncSetAttribute(gemm1_rope_fill_kernel,
        cudaFuncAttributeMaxDynamicSharedMemorySize, SMEM_A_BYTES);
    cudaFuncSetAttribute(attn_logits_kernel,
        cudaFuncAttributeMaxDynamicSharedMemorySize, SMEM_B_BYTES);

    sincos_kernel<<<64, 512>>>();
    prep_x_kernel<<<512, 256>>>(X);
    prep_w_kernel<<<dim3(64, 32), dim3(32, 8)>>>(W);
    gemm1_rope_fill_kernel<<<GEMM_CTAS + FILL_CTAS, 128, SMEM_A_BYTES>>>(bias, tok, out);
    attn_logits_kernel<<<dim3(8, 8, 64), 256, SMEM_B_BYTES>>>(tok, out);
}

// round 13
// speedup vs baseline: 1.0973x; 1.0274x over previous
#include <cuda_runtime.h>
#include <cuda_fp16.h>
#include <cstdint>

#define Bdim  4
#define Sdim  1024
#define Hdim  1024
#define ENTn  16
#define INNER 64
#define NOUT  2048
#define NEGC  1.0e12f
#define WSCALE 256.0f
#define WINV   0.00390625f

// Scratch (allocation-free rule: __device__ globals)
__device__ __half g_Q[Bdim*ENTn*Sdim*INNER];   // [b][h][s][d] f16
__device__ __half g_K[Bdim*ENTn*Sdim*INNER];
__device__ uint8_t g_X8[Bdim*Sdim*Hdim];       // X in e4m3 [m][k]
__device__ uint8_t g_W8[NOUT*Hdim];            // (W*256)^T in e4m3 [n][k]
__device__ float g_sin[Sdim*(INNER/2)];        // [s][j]
__device__ float g_cos[Sdim*(INNER/2)];

__device__ __forceinline__ void cp16(void* s, const void* g){
    uint32_t sa = (uint32_t)__cvta_generic_to_shared(s);
    asm volatile("cp.async.cg.shared.global [%0], [%1], 16;" :: "r"(sa), "l"(g));
}
__device__ __forceinline__ void cp_commit(){ asm volatile("cp.async.commit_group;" ::: "memory"); }
template<int N> __device__ __forceinline__ void cp_wait(){
    asm volatile("cp.async.wait_group %0;" :: "n"(N) : "memory");
}
__device__ __forceinline__ void ldsm_x4(uint32_t* r, uint32_t addr){
    asm volatile("ldmatrix.sync.aligned.m8n8.x4.shared.b16 {%0,%1,%2,%3}, [%4];"
        : "=r"(r[0]), "=r"(r[1]), "=r"(r[2]), "=r"(r[3]) : "r"(addr));
}
// e4m3 x e4m3 -> f32, k=32 per instruction (2x f16 MACs/instr)
__device__ __forceinline__ void mma_fp8(float* c, const uint32_t* a, const uint32_t* b){
    asm volatile("mma.sync.aligned.m16n8k32.row.col.f32.e4m3.e4m3.f32 "
        "{%0,%1,%2,%3}, {%4,%5,%6,%7}, {%8,%9}, {%0,%1,%2,%3};"
        : "+f"(c[0]), "+f"(c[1]), "+f"(c[2]), "+f"(c[3])
        : "r"(a[0]), "r"(a[1]), "r"(a[2]), "r"(a[3]), "r"(b[0]), "r"(b[1]));
}
// f16 inputs, f32 accumulators (attn)
__device__ __forceinline__ void mma_f32acc(float* c, const uint32_t* a, const uint32_t* b){
    asm volatile("mma.sync.aligned.m16n8k16.row.col.f32.f16.f16.f32 "
        "{%0,%1,%2,%3}, {%4,%5,%6,%7}, {%8,%9}, {%0,%1,%2,%3};"
        : "+f"(c[0]), "+f"(c[1]), "+f"(c[2]), "+f"(c[3])
        : "r"(a[0]), "r"(a[1]), "r"(a[2]), "r"(a[3]), "r"(b[0]), "r"(b[1]));
}
__device__ __forceinline__ uint16_t f2e4m3x2(float hi, float lo){
    uint16_t u;
    asm("cvt.rn.satfinite.e4m3x2.f32 %0, %1, %2;" : "=h"(u) : "f"(hi), "f"(lo));
    return u;
}
__device__ __forceinline__ void stg_cs_f2(float* p, float x, float y){
    asm volatile("st.global.cs.v2.f32 [%0], {%1,%2};" :: "l"(p), "f"(x), "f"(y) : "memory");
}
__device__ __forceinline__ void stg_cs_f4(float* p, float4 v){
    asm volatile("st.global.cs.v4.f32 [%0], {%1,%2,%3,%4};"
        :: "l"(p), "f"(v.x), "f"(v.y), "f"(v.z), "f"(v.w) : "memory");
}

// ---------------------------------------------------------------------------
// Kernel T: RoPE sin/cos table (exact fp32 math matching jax reference)
// ---------------------------------------------------------------------------
__global__ void sincos_kernel(){
    int idx = blockIdx.x*blockDim.x + threadIdx.x;
    if (idx >= Sdim*32) return;
    int s = idx >> 5, j = idx & 31;
    float freq = powf(10000.0f, -(float)j * 0.03125f);
    float ang  = (float)s * freq;
    g_sin[idx] = sinf(ang);
    g_cos[idx] = cosf(ang);
}

// ---------------------------------------------------------------------------
// Prep: X (f32) -> g_X8 (e4m3, unscaled; X~N(0,1) well inside range)
// ---------------------------------------------------------------------------
__global__ void prep_x_kernel(const float* __restrict__ X){
    int n4 = Bdim*Sdim*Hdim/4;
    for (int i = blockIdx.x*blockDim.x + threadIdx.x; i < n4; i += gridDim.x*blockDim.x){
        float4 v = reinterpret_cast<const float4*>(X)[i];
        uint32_t lo = f2e4m3x2(v.y, v.x);
        uint32_t hi = f2e4m3x2(v.w, v.z);
        reinterpret_cast<uint32_t*>(g_X8)[i] = lo | (hi << 16);
    }
}

// ---------------------------------------------------------------------------
// Prep: W [k][n] f32 -> g_W8 [n][k] e4m3 of (W*256) (tiled transpose)
// ---------------------------------------------------------------------------
__global__ void prep_w_kernel(const float* __restrict__ W){
    __shared__ float t[32][33];
    const int k0 = blockIdx.y*32, n0 = blockIdx.x*32;
    #pragma unroll
    for (int i = threadIdx.y; i < 32; i += 8)
        t[i][threadIdx.x] = W[(size_t)(k0+i)*NOUT + n0 + threadIdx.x];
    __syncthreads();
    #pragma unroll
    for (int i = threadIdx.y; i < 32; i += 8){
        uint16_t u = f2e4m3x2(0.0f, t[threadIdx.x][i] * WSCALE);
        g_W8[(size_t)(n0+i)*Hdim + k0 + threadIdx.x] = (uint8_t)(u & 0xFF);
    }
}

// ---------------------------------------------------------------------------
// Kernel A (fused): bid < 512 -> FP8 GEMM1 + RoPE.
//   CTA tile 128x128, 256 threads, 8 warps (4x2) of 32x64, f32 acc.
//   BK=64 bytes, 2-stage cp.async, smem row stride 80 B (16B aligned,
//   20r mod 32 bijective -> conflict-free LDSM). Per k32-step: 6 LDSM.x4
//   feed 16 QMMA (each 2x the f16 MACs) -> half the instructions of R10.
// bid >= 512 -> constant-fill CTA for one strictly-lower logits tile.
// ---------------------------------------------------------------------------
#define G1STRB 80
#define STAGE_B (128*G1STRB*2)         // A(10240) + B(10240) = 20480
#define SMEM_A_BYTES (2*STAGE_B)       // 40960 B
#define GEMM_CTAS 512
#define FILL_CTAS (64*28)

__global__ void __launch_bounds__(256, 2) gemm1_rope_fill_kernel(
    const float* __restrict__ bias, const float* __restrict__ tok,
    float* __restrict__ out)
{
    const int bid = blockIdx.x;
    const int tid = threadIdx.x;

    if (bid >= GEMM_CTAS){
        // ---- constant fill of one strictly-lower 128x128 tile ----
        int f = bid - GEMM_CTAS;
        int z = f / 28, t = f % 28;
        int mt = 1; while (t >= mt){ t -= mt; mt++; }   // mtile=mt (1..7), ntile=t
        const int ntile = t;
        float* outb = out + ((size_t)z << 20);
        const float* padp = tok + (z >> 4)*Sdim + ntile*128;

        const int n4 = (tid & 31) << 2;
        const int m0 = mt*128 + (tid >> 5);             // 8 warps: rows tid>>5 + i*8
        float4 pv = *reinterpret_cast<const float4*>(padp + n4);
        float4 val;
        val.x = (-(1.0f - pv.x)*NEGC - NEGC)*0.125f;
        val.y = (-(1.0f - pv.y)*NEGC - NEGC)*0.125f;
        val.z = (-(1.0f - pv.z)*NEGC - NEGC)*0.125f;
        val.w = (-(1.0f - pv.w)*NEGC - NEGC)*0.125f;
        const int ncol = ntile*128 + n4;
        #pragma unroll
        for (int i = 0; i < 16; i++)
            stg_cs_f4(outb + ((size_t)(m0 + i*8) << 10) + ncol, val);
        return;
    }

    // ---- FP8 GEMM1 + RoPE ----
    extern __shared__ uint8_t smu[];
    const uint32_t sbase = (uint32_t)__cvta_generic_to_shared(smu);
    const int lane = tid & 31, warp = tid >> 5;
    const int g = lane >> 2, tg = lane & 3;
    const int wm = warp >> 1, wn = warp & 1;          // 4x2 warps, 32x64 tiles
    const int ntile = bid & 15, mtile = bid >> 4;     // 16 x 32
    const uint8_t* Xb = g_X8 + (size_t)mtile*128*Hdim;
    const uint8_t* Wb = g_W8 + (size_t)ntile*128*Hdim;

    const int l7   = lane & 7;
    const int selA_r  = ((lane >> 3) & 1) * 8;
    const int selA_cb = (lane >> 4) * 16;
    const int selB_r  = (lane >> 4) * 8;
    const int selB_cb = ((lane >> 3) & 1) * 16;

    float acc[2][8][4];
    #pragma unroll
    for (int a=0;a<2;a++)
        #pragma unroll
        for (int bq=0;bq<8;bq++)
            #pragma unroll
            for (int k=0;k<4;k++) acc[a][bq][k]=0.f;

    auto load_stage = [&](int ks, int b){
        uint8_t* Ad = smu + b*STAGE_B;
        uint8_t* Bd = Ad + 128*G1STRB;
        const uint8_t* xs = Xb + ks*64;
        const uint8_t* ws = Wb + ks*64;
        #pragma unroll
        for (int i=0;i<2;i++){
            int c = tid + i*256;                  // 0..511
            int row = c >> 2, cb = (c & 3) << 4;  // 128 rows x 4 chunks of 16B
            cp16(Ad + row*G1STRB + cb, xs + (size_t)row*Hdim + cb);
            cp16(Bd + row*G1STRB + cb, ws + (size_t)row*Hdim + cb);
        }
        cp_commit();
    };

    load_stage(0, 0);
    int buf = 0;
    for (int ks = 0; ks < 16; ks++){
        if (ks < 15){ load_stage(ks+1, buf^1); cp_wait<1>(); }
        else        { cp_wait<0>(); }
        __syncthreads();
        const uint32_t abase = sbase + buf*STAGE_B;
        const uint32_t bbase = abase + 128*G1STRB;
        #pragma unroll
        for (int kk=0; kk<2; kk++){
            const int k0b = kk*32;
            uint32_t af[2][4], bf[8][2];
            #pragma unroll
            for (int mt=0; mt<2; mt++){
                int row = wm*32 + mt*16 + selA_r + l7;
                ldsm_x4(af[mt], abase + row*G1STRB + k0b + selA_cb);
            }
            #pragma unroll
            for (int ntp=0; ntp<4; ntp++){
                int row = wn*64 + ntp*16 + selB_r + l7;
                uint32_t q[4];
                ldsm_x4(q, bbase + row*G1STRB + k0b + selB_cb);
                bf[2*ntp  ][0] = q[0]; bf[2*ntp  ][1] = q[1];
                bf[2*ntp+1][0] = q[2]; bf[2*ntp+1][1] = q[3];
            }
            #pragma unroll
            for (int mt=0; mt<2; mt++)
                #pragma unroll
                for (int nt=0; nt<8; nt++)
                    mma_fp8(acc[mt][nt], af[mt], bf[nt]);
        }
        __syncthreads();
        buf ^= 1;
    }

    // Epilogue: un-scale (1/256) + bias + RoPE, f16 out
    #pragma unroll
    for (int nt=0; nt<8; nt++){
        const int n_loc = wn*64 + nt*8 + 2*tg;
        const int c = ntile*128 + n_loc;         // even
        const int h = c >> 7, r = c & 127;
        const int d = r & 63, jj = d >> 1;
        __half* dst = (r < 64) ? g_Q : g_K;
        const float b0 = bias[c], b1 = bias[c+1];
        #pragma unroll
        for (int mt=0; mt<2; mt++){
            #pragma unroll
            for (int p=0; p<2; p++){
                int m = mtile*128 + wm*32 + mt*16 + g + p*8;
                int bb = m >> 10, s = m & 1023;
                float sv = g_sin[s*32 + jj], cv = g_cos[s*32 + jj];
                float v0 = acc[mt][nt][2*p]   * WINV + b0;
                float v1 = acc[mt][nt][2*p+1] * WINV + b1;
                __half2 o;
                o.x = __float2half_rn(v0*cv - v1*sv);
                o.y = __float2half_rn(v1*cv + v0*sv);
                int idx = ((bb*ENTn + h)*Sdim + s)*INNER + d;
                *reinterpret_cast<__half2*>(dst + idx) = o;
            }
        }
    }
}

// ---------------------------------------------------------------------------
// Kernel B: upper/diagonal logits tiles only (lower tiles pre-filled by
// kernel A's filler CTAs). f16 m16n8k16 (f32 acc), ldmatrix, streaming stores.
// ---------------------------------------------------------------------------
#define QK2STR 72
#define SMEM_B_BYTES (2*128*QK2STR*2)

__global__ void __launch_bounds__(256) attn_logits_kernel(
    const float* __restrict__ tok, float* __restrict__ out)
{
    const int ntile = blockIdx.x, mtile = blockIdx.y, z = blockIdx.z;
    if (ntile < mtile) return;                 // pre-filled by kernel A
    const int bidx = z >> 4;
    const int tid = threadIdx.x;
    float* outb = out + ((size_t)z << 20);
    const float* padp = tok + bidx*Sdim + ntile*128;

    extern __shared__ __half smh[];
    const uint32_t sbase = (uint32_t)__cvta_generic_to_shared(smh);
    __half* Qs = smh;                 // [128][QK2STR]
    __half* Ks = smh + 128*QK2STR;
    __shared__ float pad_s[128];
    if (tid < 128) pad_s[tid] = padp[tid];

    const __half* Qg = g_Q + ((size_t)z*Sdim + (size_t)mtile*128)*INNER;
    const __half* Kg = g_K + ((size_t)z*Sdim + (size_t)ntile*128)*INNER;
    #pragma unroll
    for (int i=0;i<4;i++){
        int t = tid + i*256;
        int row = t >> 3, ch = (t & 7) << 3;
        cp16(Qs + row*QK2STR + ch, Qg + row*INNER + ch);
        cp16(Ks + row*QK2STR + ch, Kg + row*INNER + ch);
    }
    cp_commit();
    cp_wait<0>();
    __syncthreads();

    const int lane = tid & 31, warp = tid >> 5;
    const int g = lane >> 2, tg = lane & 3;
    const int wm = warp >> 1, wn = warp & 1;
    const int l7   = lane & 7;
    const int selA_r = ((lane >> 3) & 1) * 8;
    const int selA_c = (lane >> 4) * 8;
    const int selB_r = (lane >> 4) * 8;
    const int selB_c = ((lane >> 3) & 1) * 8;
    const uint32_t qbase = sbase;
    const uint32_t kbase = sbase + (128*QK2STR)*2;

    float acc[2][8][4];
    #pragma unroll
    for (int a=0;a<2;a++)
        #pragma unroll
        for (int bq=0;bq<8;bq++)
            #pragma unroll
            for (int k=0;k<4;k++) acc[a][bq][k]=0.f;

    #pragma unroll
    for (int kk=0; kk<4; kk++){
        const int k0 = kk*16;
        uint32_t af[2][4], bf[8][2];
        #pragma unroll
        for (int mt=0; mt<2; mt++){
            int row = wm*32 + mt*16 + selA_r + l7;
            ldsm_x4(af[mt], qbase + (row*QK2STR + k0 + selA_c)*2);
        }
        #pragma unroll
        for (int ntp=0; ntp<4; ntp++){
            int row = wn*64 + ntp*16 + selB_r + l7;
            uint32_t q[4];
            ldsm_x4(q, kbase + (row*QK2STR + k0 + selB_c)*2);
            bf[2*ntp  ][0] = q[0]; bf[2*ntp  ][1] = q[1];
            bf[2*ntp+1][0] = q[2]; bf[2*ntp+1][1] = q[3];
        }
        #pragma unroll
        for (int mt=0; mt<2; mt++)
            #pragma unroll
            for (int nt=0; nt<8; nt++)
                mma_f32acc(acc[mt][nt], af[mt], bf[nt]);
    }

    #pragma unroll
    for (int mt=0; mt<2; mt++){
        #pragma unroll
        for (int nt=0; nt<8; nt++){
            const int n_loc = wn*64 + nt*8 + 2*tg;
            const int n = ntile*128 + n_loc;
            const float p0 = pad_s[n_loc], p1 = pad_s[n_loc+1];
            #pragma unroll
            for (int p=0; p<2; p++){
                const int m = mtile*128 + wm*32 + mt*16 + g + p*8;
                float v0 = acc[mt][nt][2*p]   * p0 - (1.0f - p0)*NEGC - ((n   < m) ? NEGC : 0.0f);
                float v1 = acc[mt][nt][2*p+1] * p1 - (1.0f - p1)*NEGC - ((n+1 < m) ? NEGC : 0.0f);
                stg_cs_f2(outb + ((size_t)m << 10) + n, v0*0.125f, v1*0.125f);
            }
        }
    }
}

// ---------------------------------------------------------------------------
extern "C" void kernel_launch(void* const* d_in, const int* in_sizes, int n_in,
                              void* d_out, int out_size)
{
    const float* X    = (const float*)d_in[0];
    const float* W    = (const float*)d_in[1];
    const float* bias = (const float*)d_in[2];
    const float* tok  = (const float*)d_in[3];
    float* out = (float*)d_out;

    cudaFuncSetAttribute(gemm1_rope_fill_kernel,
        cudaFuncAttributeMaxDynamicSharedMemorySize, SMEM_A_BYTES);
    cudaFuncSetAttribute(attn_logits_kernel,
        cudaFuncAttributeMaxDynamicSharedMemorySize, SMEM_B_BYTES);

    sincos_kernel<<<64, 512>>>();
    prep_x_kernel<<<512, 256>>>(X);
    prep_w_kernel<<<dim3(64, 32), dim3(32, 8)>>>(W);
    gemm1_rope_fill_kernel<<<GEMM_CTAS + FILL_CTAS, 256, SMEM_A_BYTES>>>(bias, tok, out);
    attn_logits_kernel<<<dim3(8, 8, 64), 256, SMEM_B_BYTES>>>(tok, out);
}

// round 14
// speedup vs baseline: 1.1620x; 1.0589x over previous
#include <cuda_runtime.h>
#include <cuda_fp16.h>
#include <cstdint>

#define Bdim  4
#define Sdim  1024
#define Hdim  1024
#define ENTn  16
#define INNER 64
#define NOUT  2048
#define NEGC  1.0e12f
#define WSCALE 256.0f
#define WINV   0.00390625f

// Scratch (allocation-free rule: __device__ globals)
__device__ __half g_Q[Bdim*ENTn*Sdim*INNER];   // [b][h][s][d] f16
__device__ __half g_K[Bdim*ENTn*Sdim*INNER];
__device__ uint8_t g_X8[Bdim*Sdim*Hdim];       // X in e4m3 [m][k]
__device__ uint8_t g_W8[NOUT*Hdim];            // (W*256)^T in e4m3 [n][k]
__device__ float g_sin[Sdim*(INNER/2)];        // [s][j]
__device__ float g_cos[Sdim*(INNER/2)];
__device__ int g_done[ENTn];                   // per-head gemm completion counters

__device__ __forceinline__ void cp16(void* s, const void* g){
    uint32_t sa = (uint32_t)__cvta_generic_to_shared(s);
    asm volatile("cp.async.cg.shared.global [%0], [%1], 16;" :: "r"(sa), "l"(g));
}
__device__ __forceinline__ void cp_commit(){ asm volatile("cp.async.commit_group;" ::: "memory"); }
template<int N> __device__ __forceinline__ void cp_wait(){
    asm volatile("cp.async.wait_group %0;" :: "n"(N) : "memory");
}
__device__ __forceinline__ void ldsm_x4(uint32_t* r, uint32_t addr){
    asm volatile("ldmatrix.sync.aligned.m8n8.x4.shared.b16 {%0,%1,%2,%3}, [%4];"
        : "=r"(r[0]), "=r"(r[1]), "=r"(r[2]), "=r"(r[3]) : "r"(addr));
}
__device__ __forceinline__ void mma_fp8(float* c, const uint32_t* a, const uint32_t* b){
    asm volatile("mma.sync.aligned.m16n8k32.row.col.f32.e4m3.e4m3.f32 "
        "{%0,%1,%2,%3}, {%4,%5,%6,%7}, {%8,%9}, {%0,%1,%2,%3};"
        : "+f"(c[0]), "+f"(c[1]), "+f"(c[2]), "+f"(c[3])
        : "r"(a[0]), "r"(a[1]), "r"(a[2]), "r"(a[3]), "r"(b[0]), "r"(b[1]));
}
__device__ __forceinline__ void mma_f32acc(float* c, const uint32_t* a, const uint32_t* b){
    asm volatile("mma.sync.aligned.m16n8k16.row.col.f32.f16.f16.f32 "
        "{%0,%1,%2,%3}, {%4,%5,%6,%7}, {%8,%9}, {%0,%1,%2,%3};"
        : "+f"(c[0]), "+f"(c[1]), "+f"(c[2]), "+f"(c[3])
        : "r"(a[0]), "r"(a[1]), "r"(a[2]), "r"(a[3]), "r"(b[0]), "r"(b[1]));
}
__device__ __forceinline__ uint16_t f2e4m3x2(float hi, float lo){
    uint16_t u;
    asm("cvt.rn.satfinite.e4m3x2.f32 %0, %1, %2;" : "=h"(u) : "f"(hi), "f"(lo));
    return u;
}
__device__ __forceinline__ void stg_cs_f2(float* p, float x, float y){
    asm volatile("st.global.cs.v2.f32 [%0], {%1,%2};" :: "l"(p), "f"(x), "f"(y) : "memory");
}
__device__ __forceinline__ void stg_cs_f4(float* p, float4 v){
    asm volatile("st.global.cs.v4.f32 [%0], {%1,%2,%3,%4};"
        :: "l"(p), "f"(v.x), "f"(v.y), "f"(v.z), "f"(v.w) : "memory");
}

// ---------------------------------------------------------------------------
// Kernel T: RoPE sin/cos table + reset per-head counters (every replay)
// ---------------------------------------------------------------------------
__global__ void sincos_kernel(){
    int idx = blockIdx.x*blockDim.x + threadIdx.x;
    if (blockIdx.x == 0 && threadIdx.x < ENTn) g_done[threadIdx.x] = 0;
    if (idx >= Sdim*32) return;
    int s = idx >> 5, j = idx & 31;
    float freq = powf(10000.0f, -(float)j * 0.03125f);
    float ang  = (float)s * freq;
    g_sin[idx] = sinf(ang);
    g_cos[idx] = cosf(ang);
}

// ---------------------------------------------------------------------------
// Prep: X (f32) -> g_X8 (e4m3)
// ---------------------------------------------------------------------------
__global__ void prep_x_kernel(const float* __restrict__ X){
    int n4 = Bdim*Sdim*Hdim/4;
    for (int i = blockIdx.x*blockDim.x + threadIdx.x; i < n4; i += gridDim.x*blockDim.x){
        float4 v = reinterpret_cast<const float4*>(X)[i];
        uint32_t lo = f2e4m3x2(v.y, v.x);
        uint32_t hi = f2e4m3x2(v.w, v.z);
        reinterpret_cast<uint32_t*>(g_X8)[i] = lo | (hi << 16);
    }
}

// ---------------------------------------------------------------------------
// Prep: W [k][n] f32 -> g_W8 [n][k] e4m3 of (W*256) (tiled transpose)
// ---------------------------------------------------------------------------
__global__ void prep_w_kernel(const float* __restrict__ W){
    __shared__ float t[32][33];
    const int k0 = blockIdx.y*32, n0 = blockIdx.x*32;
    #pragma unroll
    for (int i = threadIdx.y; i < 32; i += 8)
        t[i][threadIdx.x] = W[(size_t)(k0+i)*NOUT + n0 + threadIdx.x];
    __syncthreads();
    #pragma unroll
    for (int i = threadIdx.y; i < 32; i += 8){
        uint16_t u = f2e4m3x2(0.0f, t[threadIdx.x][i] * WSCALE);
        g_W8[(size_t)(n0+i)*Hdim + k0 + threadIdx.x] = (uint8_t)(u & 0xFF);
    }
}

// ---------------------------------------------------------------------------
// MEGA kernel: one launch, three CTA roles in FIFO-safe bid order.
//  bid < 512:           FP8 GEMM1 + RoPE -> g_Q/g_K (head = bid>>5; all 32
//                       mtiles of a head are consecutive bids -> heads
//                       complete in order). Signals g_done[head] (release).
//  512 <= bid < 2304:   constant fill of strictly-lower logits tiles (no deps).
//  bid >= 2304:         attn tile; spins (acquire) until g_done[h]==32, then
//                       computes Q.K^T upper/diag tile. Ordered by head.
// Progress: all gemm bids precede all attn bids; gemm CTAs never wait.
// ---------------------------------------------------------------------------
#define G1STRB 80
#define STAGE_B (128*G1STRB*2)
#define SMEM_MEGA 40960                 // max(gemm 40960, attn 36864+512)
#define GEMM_CTAS 512
#define FILL_CTAS (64*28)
#define ATTN_CTAS (64*36)
#define QK2STR 72

__global__ void __launch_bounds__(256, 2) mega_kernel(
    const float* __restrict__ bias, const float* __restrict__ tok,
    float* __restrict__ out)
{
    const int bid = blockIdx.x;
    const int tid = threadIdx.x;
    extern __shared__ uint8_t smu[];
    const uint32_t sbase = (uint32_t)__cvta_generic_to_shared(smu);
    const int lane = tid & 31, warp = tid >> 5;
    const int g = lane >> 2, tg = lane & 3;
    const int l7 = lane & 7;

    if (bid < GEMM_CTAS){
        // ================= FP8 GEMM1 + RoPE =================
        const int ntile = bid >> 5, mtile = bid & 31;     // head-major
        const int wm = warp >> 1, wn = warp & 1;          // 4x2 warps, 32x64
        const uint8_t* Xb = g_X8 + (size_t)mtile*128*Hdim;
        const uint8_t* Wb = g_W8 + (size_t)ntile*128*Hdim;

        const int selA_r  = ((lane >> 3) & 1) * 8;
        const int selA_cb = (lane >> 4) * 16;
        const int selB_r  = (lane >> 4) * 8;
        const int selB_cb = ((lane >> 3) & 1) * 16;

        float acc[2][8][4];
        #pragma unroll
        for (int a=0;a<2;a++)
            #pragma unroll
            for (int bq=0;bq<8;bq++)
                #pragma unroll
                for (int k=0;k<4;k++) acc[a][bq][k]=0.f;

        auto load_stage = [&](int ks, int b){
            uint8_t* Ad = smu + b*STAGE_B;
            uint8_t* Bd = Ad + 128*G1STRB;
            const uint8_t* xs = Xb + ks*64;
            const uint8_t* ws = Wb + ks*64;
            #pragma unroll
            for (int i=0;i<2;i++){
                int c = tid + i*256;
                int row = c >> 2, cb = (c & 3) << 4;
                cp16(Ad + row*G1STRB + cb, xs + (size_t)row*Hdim + cb);
                cp16(Bd + row*G1STRB + cb, ws + (size_t)row*Hdim + cb);
            }
            cp_commit();
        };

        load_stage(0, 0);
        int buf = 0;
        for (int ks = 0; ks < 16; ks++){
            if (ks < 15){ load_stage(ks+1, buf^1); cp_wait<1>(); }
            else        { cp_wait<0>(); }
            __syncthreads();
            const uint32_t abase = sbase + buf*STAGE_B;
            const uint32_t bbase = abase + 128*G1STRB;
            #pragma unroll
            for (int kk=0; kk<2; kk++){
                const int k0b = kk*32;
                uint32_t af[2][4], bf[8][2];
                #pragma unroll
                for (int mt=0; mt<2; mt++){
                    int row = wm*32 + mt*16 + selA_r + l7;
                    ldsm_x4(af[mt], abase + row*G1STRB + k0b + selA_cb);
                }
                #pragma unroll
                for (int ntp=0; ntp<4; ntp++){
                    int row = wn*64 + ntp*16 + selB_r + l7;
                    uint32_t q[4];
                    ldsm_x4(q, bbase + row*G1STRB + k0b + selB_cb);
                    bf[2*ntp  ][0] = q[0]; bf[2*ntp  ][1] = q[1];
                    bf[2*ntp+1][0] = q[2]; bf[2*ntp+1][1] = q[3];
                }
                #pragma unroll
                for (int mt=0; mt<2; mt++)
                    #pragma unroll
                    for (int nt=0; nt<8; nt++)
                        mma_fp8(acc[mt][nt], af[mt], bf[nt]);
            }
            __syncthreads();
            buf ^= 1;
        }

        // Epilogue: un-scale + bias + RoPE, f16 out
        #pragma unroll
        for (int nt=0; nt<8; nt++){
            const int n_loc = wn*64 + nt*8 + 2*tg;
            const int c = ntile*128 + n_loc;
            const int h = c >> 7, r = c & 127;
            const int d = r & 63, jj = d >> 1;
            __half* dst = (r < 64) ? g_Q : g_K;
            const float b0 = bias[c], b1 = bias[c+1];
            #pragma unroll
            for (int mt=0; mt<2; mt++){
                #pragma unroll
                for (int p=0; p<2; p++){
                    int m = mtile*128 + wm*32 + mt*16 + g + p*8;
                    int bb = m >> 10, s = m & 1023;
                    float sv = g_sin[s*32 + jj], cv = g_cos[s*32 + jj];
                    float v0 = acc[mt][nt][2*p]   * WINV + b0;
                    float v1 = acc[mt][nt][2*p+1] * WINV + b1;
                    __half2 o;
                    o.x = __float2half_rn(v0*cv - v1*sv);
                    o.y = __float2half_rn(v1*cv + v0*sv);
                    int idx = ((bb*ENTn + h)*Sdim + s)*INNER + d;
                    *reinterpret_cast<__half2*>(dst + idx) = o;
                }
            }
        }
        // Signal: this head's (mtile) slice of Q/K is globally visible.
        __threadfence();
        __syncthreads();
        if (tid == 0)
            asm volatile("red.release.gpu.global.add.s32 [%0], 1;"
                         :: "l"(&g_done[ntile]) : "memory");
        return;
    }

    if (bid < GEMM_CTAS + FILL_CTAS){
        // ================= constant fill (strictly-lower tiles) =============
        int f = bid - GEMM_CTAS;
        int z = f / 28, t = f % 28;
        int mt = 1; while (t >= mt){ t -= mt; mt++; }
        const int ntile = t;
        float* outb = out + ((size_t)z << 20);
        const float* padp = tok + (z >> 4)*Sdim + ntile*128;

        const int n4 = (lane) << 2;
        const int m0 = mt*128 + warp;
        float4 pv = *reinterpret_cast<const float4*>(padp + n4);
        float4 val;
        val.x = (-(1.0f - pv.x)*NEGC - NEGC)*0.125f;
        val.y = (-(1.0f - pv.y)*NEGC - NEGC)*0.125f;
        val.z = (-(1.0f - pv.z)*NEGC - NEGC)*0.125f;
        val.w = (-(1.0f - pv.w)*NEGC - NEGC)*0.125f;
        const int ncol = ntile*128 + n4;
        #pragma unroll
        for (int i = 0; i < 16; i++)
            stg_cs_f4(outb + ((size_t)(m0 + i*8) << 10) + ncol, val);
        return;
    }

    // ================= attn tile (upper/diagonal) =================
    {
        int a = bid - (GEMM_CTAS + FILL_CTAS);
        const int h = a / 144;              // head-major: matches gemm order
        int r2 = a % 144;
        const int bI = r2 / 36;
        int t = r2 % 36;
        int mtile = 0; while (t >= 8 - mtile){ t -= 8 - mtile; mtile++; }
        const int ntile = mtile + t;
        const int z = bI*ENTn + h;

        // Wait for all 32 gemm CTAs of this head (acquire)
        if (tid == 0){
            int v;
            do {
                asm volatile("ld.acquire.gpu.global.s32 %0, [%1];"
                             : "=r"(v) : "l"(&g_done[h]));
            } while (v < 32);
        }
        __syncthreads();

        float* outb = out + ((size_t)z << 20);
        const float* padp = tok + bI*Sdim + ntile*128;
        __half* Qs = reinterpret_cast<__half*>(smu);
        __half* Ks = Qs + 128*QK2STR;
        __shared__ float pad_s[128];
        if (tid < 128) pad_s[tid] = padp[tid];

        const __half* Qg = g_Q + ((size_t)z*Sdim + (size_t)mtile*128)*INNER;
        const __half* Kg = g_K + ((size_t)z*Sdim + (size_t)ntile*128)*INNER;
        #pragma unroll
        for (int i=0;i<4;i++){
            int t2 = tid + i*256;
            int row = t2 >> 3, ch = (t2 & 7) << 3;
            cp16(Qs + row*QK2STR + ch, Qg + row*INNER + ch);
            cp16(Ks + row*QK2STR + ch, Kg + row*INNER + ch);
        }
        cp_commit();
        cp_wait<0>();
        __syncthreads();

        const int wm = warp >> 1, wn = warp & 1;
        const int selA_r = ((lane >> 3) & 1) * 8;
        const int selA_c = (lane >> 4) * 8;
        const int selB_r = (lane >> 4) * 8;
        const int selB_c = ((lane >> 3) & 1) * 8;
        const uint32_t qbase = sbase;
        const uint32_t kbase = sbase + (128*QK2STR)*2;

        float acc[2][8][4];
        #pragma unroll
        for (int aa=0;aa<2;aa++)
            #pragma unroll
            for (int bq=0;bq<8;bq++)
                #pragma unroll
                for (int k=0;k<4;k++) acc[aa][bq][k]=0.f;

        #pragma unroll
        for (int kk=0; kk<4; kk++){
            const int k0 = kk*16;
            uint32_t af[2][4], bf[8][2];
            #pragma unroll
            for (int mt=0; mt<2; mt++){
                int row = wm*32 + mt*16 + selA_r + l7;
                ldsm_x4(af[mt], qbase + (row*QK2STR + k0 + selA_c)*2);
            }
            #pragma unroll
            for (int ntp=0; ntp<4; ntp++){
                int row = wn*64 + ntp*16 + selB_r + l7;
                uint32_t q[4];
                ldsm_x4(q, kbase + (row*QK2STR + k0 + selB_c)*2);
                bf[2*ntp  ][0] = q[0]; bf[2*ntp  ][1] = q[1];
                bf[2*ntp+1][0] = q[2]; bf[2*ntp+1][1] = q[3];
            }
            #pragma unroll
            for (int mt=0; mt<2; mt++)
                #pragma unroll
                for (int nt=0; nt<8; nt++)
                    mma_f32acc(acc[mt][nt], af[mt], bf[nt]);
        }

        #pragma unroll
        for (int mt=0; mt<2; mt++){
            #pragma unroll
            for (int nt=0; nt<8; nt++){
                const int n_loc = wn*64 + nt*8 + 2*tg;
                const int n = ntile*128 + n_loc;
                const float p0 = pad_s[n_loc], p1 = pad_s[n_loc+1];
                #pragma unroll
                for (int p=0; p<2; p++){
                    const int m = mtile*128 + wm*32 + mt*16 + g + p*8;
                    float v0 = acc[mt][nt][2*p]   * p0 - (1.0f - p0)*NEGC - ((n   < m) ? NEGC : 0.0f);
                    float v1 = acc[mt][nt][2*p+1] * p1 - (1.0f - p1)*NEGC - ((n+1 < m) ? NEGC : 0.0f);
                    stg_cs_f2(outb + ((size_t)m << 10) + n, v0*0.125f, v1*0.125f);
                }
            }
        }
    }
}

// ---------------------------------------------------------------------------
extern "C" void kernel_launch(void* const* d_in, const int* in_sizes, int n_in,
                              void* d_out, int out_size)
{
    const float* X    = (const float*)d_in[0];
    const float* W    = (const float*)d_in[1];
    const float* bias = (const float*)d_in[2];
    const float* tok  = (const float*)d_in[3];
    float* out = (float*)d_out;

    cudaFuncSetAttribute(mega_kernel,
        cudaFuncAttributeMaxDynamicSharedMemorySize, SMEM_MEGA);

    sincos_kernel<<<64, 512>>>();
    prep_x_kernel<<<512, 256>>>(X);
    prep_w_kernel<<<dim3(64, 32), dim3(32, 8)>>>(W);
    mega_kernel<<<GEMM_CTAS + FILL_CTAS + ATTN_CTAS, 256, SMEM_MEGA>>>(bias, tok, out);
}